// round 13
// baseline (speedup 1.0000x reference)
#include <cuda_runtime.h>

// ---------------------------------------------------------------------------
// SSD post-process, 3 kernels:
//  K1 k_scan    : stream conf (batched loads, branchy prefilter, shared
//                 staging, bucket epilogue into 16K score bins)
//  K2 k_mid     : 1 block: cutoff suffix-scan -> DIRECT placement by exact
//                 per-bin offsets -> per-bin warp sort (32-lane shfl bitonic)
//                 -> decode top-512
//  K3 k_iou_nms : 128x256 suppression bitmask -> tick -> [last block] greedy
//                 NMS (named-register diagonal) -> output -> state reset
//  (round-12 design; fix: um must be 16B-aligned for the uint4 staging copy,
//   and all shared decls hoisted so layout is explicit)
// ---------------------------------------------------------------------------

#define NB2      16384              // score-bit bins (128-ulp)
#define BSHIFT   7
#define BASEBITS 0x3F666666u        // bits(0.9f)
#define CAP      128                // per-bin bucket capacity (max seen ~30)
#define KTOP     512
#define SELCAP   1024
#define PREF_T   2.19f              // conservative prefilter: ln(9)=2.1972

__device__ __align__(16) int  g_hist[NB2];
__device__ unsigned long long g_bucket[NB2 * CAP];   // 16MB
__device__ unsigned           g_tick3;
__device__ float4             g_box[KTOP];
__device__ float              g_area[KTOP];
__device__ float              g_score[KTOP];
__device__ __align__(16) unsigned g_mask32[KTOP * 16];

// ---------------------------------------------------------------------------
// K1: 256 threads/block, 1024 float4 (2048 priors) per block, grid 1024.
// ---------------------------------------------------------------------------
__global__ void __launch_bounds__(256) k_scan(const float4* __restrict__ conf4, int n4) {
    __shared__ unsigned long long lbuf[2048];
    __shared__ int lcount;
    int tid = threadIdx.x;
    if (tid == 0) lcount = 0;
    __syncthreads();

    int base = blockIdx.x * 1024 + tid;
    float4 v[4];
#pragma unroll
    for (int k = 0; k < 4; ++k) {
        int i4 = base + k * 256;
        v[k] = (i4 < n4) ? conf4[i4] : make_float4(0.f, 0.f, 0.f, 0.f);
    }
#pragma unroll
    for (int k = 0; k < 4; ++k) {
        int i4 = base + k * 256;
        if (v[k].y - v[k].x > PREF_T) {                      // rare (~3%)
            float s = 1.0f / (1.0f + expf(v[k].x - v[k].y)); // exact fp32 softmax
            if (s > 0.9f) {
                unsigned idx = 2u * (unsigned)i4;
                int pos = atomicAdd(&lcount, 1);
                lbuf[pos] = ((unsigned long long)__float_as_uint(s) << 32) |
                            (unsigned long long)(0xffffffffu - idx);
            }
        }
        if (v[k].w - v[k].z > PREF_T) {
            float s = 1.0f / (1.0f + expf(v[k].z - v[k].w));
            if (s > 0.9f) {
                unsigned idx = 2u * (unsigned)i4 + 1u;
                int pos = atomicAdd(&lcount, 1);
                lbuf[pos] = ((unsigned long long)__float_as_uint(s) << 32) |
                            (unsigned long long)(0xffffffffu - idx);
            }
        }
    }
    __syncthreads();

    int lc = lcount;
    for (int j = tid; j < lc; j += 256) {
        unsigned long long key = lbuf[j];
        int bin  = (int)(((unsigned)(key >> 32) - BASEBITS) >> BSHIFT);
        int slot = atomicAdd(&g_hist[bin], 1);
        if (slot < CAP) g_bucket[bin * CAP + slot] = key;
    }
}

// 32-lane descending bitonic CAS step (64-bit keys)
__device__ __forceinline__ unsigned long long bt_shfl(unsigned long long v, int j,
                                                      int k, int tid) {
    unsigned long long pv = __shfl_xor_sync(0xffffffffu, v, j);
    bool ilow   = (tid & j) == 0;
    bool maxlow = (tid & k) == 0;
    return (ilow == maxlow) ? (v > pv ? v : pv) : (v < pv ? v : pv);
}

// ---------------------------------------------------------------------------
// K2: single block of 1024.
// Bins are disjoint score ranges -> global order = (bin desc, within-bin desc).
// So: exact per-bin suffix offsets -> direct placement -> sort each bin only.
// ---------------------------------------------------------------------------
__global__ void __launch_bounds__(1024, 1) k_mid(const float4* __restrict__ loc,
                                                 const float4* __restrict__ priors) {
    __shared__ __align__(16) unsigned long long sbuf[SELCAP];
    __shared__ unsigned s_wl[256];         // worklist: off<<8 | cnt
    __shared__ int s_wtot[32], s_wsuf[32];
    __shared__ int s_cut, s_nw;
    int tid  = threadIdx.x;
    int lane = tid & 31;
    int wid  = tid >> 5;

    // per-thread: 16 bins [16*tid, 16*tid+16), counts clamped to CAP
    int cnt16[16];
    int part = 0;
#pragma unroll
    for (int q = 0; q < 4; ++q) {
        int4 h = ((const int4*)g_hist)[tid * 4 + q];
        int a = h.x > CAP ? CAP : h.x;  int b = h.y > CAP ? CAP : h.y;
        int c = h.z > CAP ? CAP : h.z;  int d = h.w > CAP ? CAP : h.w;
        cnt16[q * 4 + 0] = a; cnt16[q * 4 + 1] = b;
        cnt16[q * 4 + 2] = c; cnt16[q * 4 + 3] = d;
        part += a + b + c + d;
    }
    // suffix scan (toward higher bins)
    int suf = part;
#pragma unroll
    for (int s = 1; s < 32; s <<= 1) {
        int t = __shfl_down_sync(0xffffffffu, suf, s);
        if (lane + s < 32) suf += t;
    }
    if (lane == 0) s_wtot[wid] = suf;
    if (tid == 0) { s_cut = 0; s_nw = 0; }
    __syncthreads();
    if (wid == 0) {
        int ws = s_wtot[lane];
#pragma unroll
        for (int s = 1; s < 32; s <<= 1) {
            int t = __shfl_down_sync(0xffffffffu, ws, s);
            if (lane + s < 32) ws += t;
        }
        s_wsuf[lane] = ws;
    }
    __syncthreads();
    int S     = suf + ((wid < 31) ? s_wsuf[wid + 1] : 0);  // suffix incl my bins
    int Snext = S - part;                                   // suffix after mine
    if (S >= KTOP && Snext < KTOP) {
        int run = Snext;
#pragma unroll
        for (int r = 15; r >= 0; --r) {
            run += cnt16[r];
            if (run >= KTOP) { s_cut = tid * 16 + r; break; }
        }
    }
    sbuf[tid] = 0ull;                      // zero-pad final array
    __syncthreads();
    int cut = s_cut;

    // direct placement: bin b's keys live at [suffix(bins > b), +cnt_b)
    {
        int acc = Snext;                   // selected keys in higher threads
        for (int r = 15; r >= 0; --r) {
            int b = tid * 16 + r;
            int c = cnt16[r];
            if (b >= cut && c > 0) {
                int off = acc;
                for (int i = 0; i < c; ++i) {
                    int p = off + i;
                    if (p < SELCAP) sbuf[p] = g_bucket[b * CAP + i];
                }
                if (c >= 2 && off < SELCAP) {
                    int w = atomicAdd(&s_nw, 1);
                    if (w < 256) s_wl[w] = ((unsigned)off << 8) | (unsigned)c;
                }
                acc += c;
            }
        }
    }
    __syncthreads();

    // per-bin sort: one warp per bin segment; <=32 keys -> shfl bitonic
    int nw = s_nw;
    if (nw > 256) nw = 256;
    for (int t = wid; t < nw; t += 32) {
        unsigned e  = s_wl[t];
        int off = (int)(e >> 8);
        int cnt = (int)(e & 255u);
        if (cnt <= 32) {
            unsigned long long v = (lane < cnt && off + lane < SELCAP)
                                   ? sbuf[off + lane] : 0ull;
#pragma unroll
            for (int k = 2; k <= 32; k <<= 1)
#pragma unroll
                for (int j = k >> 1; j >= 1; j >>= 1)
                    v = bt_shfl(v, j, k, lane);
            if (lane < cnt && off + lane < SELCAP) sbuf[off + lane] = v;
        } else if (lane == 0) {            // fallback (never seen: max ~30/bin)
            for (int i = 1; i < cnt && off + i < SELCAP; ++i) {
                unsigned long long key = sbuf[off + i];
                int j = i - 1;
                while (j >= 0 && sbuf[off + j] < key) {
                    sbuf[off + j + 1] = sbuf[off + j];
                    --j;
                }
                sbuf[off + j + 1] = key;
            }
        }
    }
    __syncthreads();

    // decode top-512
    if (tid < KTOP) {
        unsigned long long key = sbuf[tid];
        float X1 = 0.f, Y1 = 0.f, X2 = 0.f, Y2 = 0.f, score = -1.0f;
        if (key != 0ull) {
            score = __uint_as_float((unsigned)(key >> 32));
            unsigned idx = 0xffffffffu - (unsigned)(key & 0xffffffffu);
            float4 l = __ldg(&loc[idx]);
            float4 p = __ldg(&priors[idx]);
            float cx = __fadd_rn(p.x, __fmul_rn(__fmul_rn(l.x, 0.1f), p.z));
            float cy = __fadd_rn(p.y, __fmul_rn(__fmul_rn(l.y, 0.1f), p.w));
            float w  = __fmul_rn(p.z, expf(__fmul_rn(l.z, 0.2f)));
            float h  = __fmul_rn(p.w, expf(__fmul_rn(l.w, 0.2f)));
            float x1 = __fsub_rn(cx, __fmul_rn(w, 0.5f));
            float y1 = __fsub_rn(cy, __fmul_rn(h, 0.5f));
            float x2 = __fadd_rn(x1, w);
            float y2 = __fadd_rn(y1, h);
            X1 = __fmul_rn(x1, 2048.0f);
            Y1 = __fmul_rn(y1, 2048.0f);
            X2 = __fmul_rn(x2, 2048.0f);
            Y2 = __fmul_rn(y2, 2048.0f);
        }
        g_box[tid]   = make_float4(X1, Y1, X2, Y2);
        g_area[tid]  = __fmul_rn(__fadd_rn(__fsub_rn(X2, X1), 1.0f),
                                 __fadd_rn(__fsub_rn(Y2, Y1), 1.0f));
        g_score[tid] = score;
    }
}

// ---------------------------------------------------------------------------
// K3: suppression bitmask (128x256) -> tick -> last block: greedy NMS
// (round-8 named-register body, measured best) -> output -> state reset.
// ---------------------------------------------------------------------------
#define DLOAD(r) unsigned d##r = um[(cb + r) * 16 + c];   // same addr = bcast
#define DSTEP(r) if (!(val & (1u << r))) val |= d##r;
#define REP32(M) M(0) M(1) M(2) M(3) M(4) M(5) M(6) M(7) \
                 M(8) M(9) M(10) M(11) M(12) M(13) M(14) M(15) \
                 M(16) M(17) M(18) M(19) M(20) M(21) M(22) M(23) \
                 M(24) M(25) M(26) M(27) M(28) M(29) M(30) M(31)

__global__ void __launch_bounds__(256) k_iou_nms(float* __restrict__ out) {
    // all shared decls hoisted; um 16B-aligned for the uint4 staging copy
    __shared__ __align__(16) unsigned um[KTOP * 16];   // 32KB
    __shared__ unsigned s_keepw[16];
    __shared__ int s_last;
    int tid = threadIdx.x;
    int T   = blockIdx.x * 256 + tid;     // 0..32767
    {
        int i  = T >> 6;
        int j0 = (T & 63) << 3;
        unsigned bits = 0u;
        float si = g_score[i];
        if (si > 0.0f) {
            float4 bi = g_box[i];
            float  ai = g_area[i];
#pragma unroll
            for (int b = 0; b < 8; ++b) {
                int j = j0 + b;
                float4 bj = g_box[j];
                float xx1 = fmaxf(bi.x, bj.x);
                float yy1 = fmaxf(bi.y, bj.y);
                float xx2 = fminf(bi.z, bj.z);
                float yy2 = fminf(bi.w, bj.w);
                float w = fmaxf(__fadd_rn(__fsub_rn(xx2, xx1), 1.0f), 0.0f);
                float h = fmaxf(__fadd_rn(__fsub_rn(yy2, yy1), 1.0f), 0.0f);
                float inter = __fmul_rn(w, h);
                float uni = __fsub_rn(__fadd_rn(ai, g_area[j]), inter);
                if (j > i && inter > __fmul_rn(0.4f, uni)) bits |= 1u << b;
            }
        }
        ((unsigned char*)g_mask32)[T] = (unsigned char)bits;
    }

    __threadfence();
    __syncthreads();
    if (tid == 0) s_last = (atomicAdd(&g_tick3, 1u) == gridDim.x - 1) ? 1 : 0;
    __syncthreads();
    if (!s_last) return;

    // ---- last block: serial greedy NMS + output + state reset ----
    for (int w = tid; w < KTOP * 4; w += 256)
        ((uint4*)um)[w] = ((const uint4*)g_mask32)[w];
    __syncthreads();

    if (tid < 32) {
        int lane = tid;
        int wlo  = lane & 15;
        int rb   = (lane < 16) ? 0 : 16;  // row split across the warp
        unsigned rem = 0u;
        for (int c = 0; c < 16; ++c) {
            unsigned val = __shfl_sync(0xffffffffu, rem, c);
            int cb = c * 32;
            REP32(DLOAD)                  // broadcast LDS into named regs
            REP32(DSTEP)                  // 32-step serial closure
            unsigned keep = ~val;
            // cross-chunk: 16 gated ORs per lane (rows split 0-15 / 16-31)
            unsigned acc = 0u;
#pragma unroll
            for (int q = 0; q < 16; ++q) {
                int r = rb + q;
                unsigned m = um[(cb + r) * 16 + wlo];
                acc |= ((keep >> r) & 1u) ? m : 0u;
            }
            acc |= __shfl_xor_sync(0xffffffffu, acc, 16);
            if (lane < 16) rem |= acc;
        }
        if (tid < 16) s_keepw[tid] = rem;
    }
    __syncthreads();

    const float inv = 1.0f / 2048.0f;     // exact
#pragma unroll
    for (int h = 0; h < 2; ++h) {
        int r = tid + h * 256;
        float sc = g_score[r];
        bool kept = (sc > 0.0f) && !((s_keepw[r >> 5] >> (r & 31)) & 1u);
        float4 b = g_box[r];
        out[r * 5 + 0] = kept ? __fmul_rn(b.x, inv) : 0.0f;
        out[r * 5 + 1] = kept ? __fmul_rn(b.y, inv) : 0.0f;
        out[r * 5 + 2] = kept ? __fmul_rn(b.z, inv) : 0.0f;
        out[r * 5 + 3] = kept ? __fmul_rn(b.w, inv) : 0.0f;
        out[r * 5 + 4] = kept ? sc : 0.0f;
    }

    // state reset for the next graph replay (zero-initialized at load)
    for (int i = tid; i < NB2; i += 256) g_hist[i] = 0;
    if (tid == 0) g_tick3 = 0u;
}

// ---------------------------------------------------------------------------
extern "C" void kernel_launch(void* const* d_in, const int* in_sizes, int n_in,
                              void* d_out, int out_size) {
    const float4* loc    = (const float4*)d_in[0];   // [N,4]
    const float4* conf4  = (const float4*)d_in[1];   // [N,2] as float4 pairs
    const float4* priors = (const float4*)d_in[2];   // [N,4]
    float* out = (float*)d_out;                      // [512,5]
    int n  = in_sizes[0] / 4;
    int n4 = n >> 1;

    k_scan<<<(n4 + 1023) / 1024, 256>>>(conf4, n4);
    k_mid<<<1, 1024>>>(loc, priors);
    k_iou_nms<<<128, 256>>>(out);
}

// round 14
// speedup vs baseline: 1.0534x; 1.0534x over previous
#include <cuda_runtime.h>

// ---------------------------------------------------------------------------
// SSD post-process, 4 kernels — every piece is the measured-best variant:
//  K1 k_scan : round-13 streaming scan (9.5us measured, 1.77TB/s)
//  K2 k_mid  : direct placement by exact per-bin suffix offsets + per-bin
//              warp sorts (replaces 55-stage bitonic)
//  K3 k_iou  : standalone suppression bitmask (launch boundary = barrier;
//              tick-join variants measured slower in rounds 5/13)
//  K4 k_nms  : standalone greedy NMS, round-8 named-register closure body
//              (12.8us measured best) + halved cross-chunk from round 13
// ---------------------------------------------------------------------------

#define NB2      16384              // score-bit bins (128-ulp)
#define BSHIFT   7
#define BASEBITS 0x3F666666u        // bits(0.9f)
#define CAP      128                // per-bin bucket capacity (max seen ~30)
#define KTOP     512
#define SELCAP   1024
#define PREF_T   2.19f              // conservative prefilter: ln(9)=2.1972

__device__ __align__(16) int  g_hist[NB2];
__device__ unsigned long long g_bucket[NB2 * CAP];   // 16MB
__device__ float4             g_box[KTOP];
__device__ float              g_area[KTOP];
__device__ float              g_score[KTOP];
__device__ __align__(16) unsigned g_mask32[KTOP * 16];

// ---------------------------------------------------------------------------
// K1: 256 threads/block, 1024 float4 (2048 priors) per block, grid 1024.
// ---------------------------------------------------------------------------
__global__ void __launch_bounds__(256) k_scan(const float4* __restrict__ conf4, int n4) {
    __shared__ unsigned long long lbuf[2048];
    __shared__ int lcount;
    int tid = threadIdx.x;
    if (tid == 0) lcount = 0;
    __syncthreads();

    int base = blockIdx.x * 1024 + tid;
    float4 v[4];
#pragma unroll
    for (int k = 0; k < 4; ++k) {
        int i4 = base + k * 256;
        v[k] = (i4 < n4) ? conf4[i4] : make_float4(0.f, 0.f, 0.f, 0.f);
    }
#pragma unroll
    for (int k = 0; k < 4; ++k) {
        int i4 = base + k * 256;
        if (v[k].y - v[k].x > PREF_T) {                      // rare (~3%)
            float s = 1.0f / (1.0f + expf(v[k].x - v[k].y)); // exact fp32 softmax
            if (s > 0.9f) {
                unsigned idx = 2u * (unsigned)i4;
                int pos = atomicAdd(&lcount, 1);
                lbuf[pos] = ((unsigned long long)__float_as_uint(s) << 32) |
                            (unsigned long long)(0xffffffffu - idx);
            }
        }
        if (v[k].w - v[k].z > PREF_T) {
            float s = 1.0f / (1.0f + expf(v[k].z - v[k].w));
            if (s > 0.9f) {
                unsigned idx = 2u * (unsigned)i4 + 1u;
                int pos = atomicAdd(&lcount, 1);
                lbuf[pos] = ((unsigned long long)__float_as_uint(s) << 32) |
                            (unsigned long long)(0xffffffffu - idx);
            }
        }
    }
    __syncthreads();

    int lc = lcount;
    for (int j = tid; j < lc; j += 256) {
        unsigned long long key = lbuf[j];
        int bin  = (int)(((unsigned)(key >> 32) - BASEBITS) >> BSHIFT);
        int slot = atomicAdd(&g_hist[bin], 1);
        if (slot < CAP) g_bucket[bin * CAP + slot] = key;
    }
}

// 32-lane descending bitonic CAS step (64-bit keys)
__device__ __forceinline__ unsigned long long bt_shfl(unsigned long long v, int j,
                                                      int k, int tid) {
    unsigned long long pv = __shfl_xor_sync(0xffffffffu, v, j);
    bool ilow   = (tid & j) == 0;
    bool maxlow = (tid & k) == 0;
    return (ilow == maxlow) ? (v > pv ? v : pv) : (v < pv ? v : pv);
}

// ---------------------------------------------------------------------------
// K2: single block of 1024.
// Bins are disjoint score ranges -> global order = (bin desc, within-bin desc).
// Exact per-bin suffix offsets -> direct placement -> sort each bin only.
// ---------------------------------------------------------------------------
__global__ void __launch_bounds__(1024, 1) k_mid(const float4* __restrict__ loc,
                                                 const float4* __restrict__ priors) {
    __shared__ __align__(16) unsigned long long sbuf[SELCAP];
    __shared__ unsigned s_wl[256];         // worklist: off<<8 | cnt
    __shared__ int s_wtot[32], s_wsuf[32];
    __shared__ int s_cut, s_nw;
    int tid  = threadIdx.x;
    int lane = tid & 31;
    int wid  = tid >> 5;

    // per-thread: 16 bins [16*tid, 16*tid+16), counts clamped to CAP
    int cnt16[16];
    int part = 0;
#pragma unroll
    for (int q = 0; q < 4; ++q) {
        int4 h = ((const int4*)g_hist)[tid * 4 + q];
        int a = h.x > CAP ? CAP : h.x;  int b = h.y > CAP ? CAP : h.y;
        int c = h.z > CAP ? CAP : h.z;  int d = h.w > CAP ? CAP : h.w;
        cnt16[q * 4 + 0] = a; cnt16[q * 4 + 1] = b;
        cnt16[q * 4 + 2] = c; cnt16[q * 4 + 3] = d;
        part += a + b + c + d;
    }
    // suffix scan (toward higher bins)
    int suf = part;
#pragma unroll
    for (int s = 1; s < 32; s <<= 1) {
        int t = __shfl_down_sync(0xffffffffu, suf, s);
        if (lane + s < 32) suf += t;
    }
    if (lane == 0) s_wtot[wid] = suf;
    if (tid == 0) { s_cut = 0; s_nw = 0; }
    __syncthreads();
    if (wid == 0) {
        int ws = s_wtot[lane];
#pragma unroll
        for (int s = 1; s < 32; s <<= 1) {
            int t = __shfl_down_sync(0xffffffffu, ws, s);
            if (lane + s < 32) ws += t;
        }
        s_wsuf[lane] = ws;
    }
    __syncthreads();
    int S     = suf + ((wid < 31) ? s_wsuf[wid + 1] : 0);  // suffix incl my bins
    int Snext = S - part;                                   // suffix after mine
    if (S >= KTOP && Snext < KTOP) {
        int run = Snext;
#pragma unroll
        for (int r = 15; r >= 0; --r) {
            run += cnt16[r];
            if (run >= KTOP) { s_cut = tid * 16 + r; break; }
        }
    }
    sbuf[tid] = 0ull;                      // zero-pad final array
    __syncthreads();
    int cut = s_cut;

    // direct placement: bin b's keys live at [suffix(bins > b), +cnt_b)
    {
        int acc = Snext;                   // selected keys in higher threads
        for (int r = 15; r >= 0; --r) {
            int b = tid * 16 + r;
            int c = cnt16[r];
            if (b >= cut && c > 0) {
                int off = acc;
                for (int i = 0; i < c; ++i) {
                    int p = off + i;
                    if (p < SELCAP) sbuf[p] = g_bucket[b * CAP + i];
                }
                if (c >= 2 && off < SELCAP) {
                    int w = atomicAdd(&s_nw, 1);
                    if (w < 256) s_wl[w] = ((unsigned)off << 8) | (unsigned)c;
                }
                acc += c;
            }
        }
    }
    __syncthreads();

    // per-bin sort: one warp per bin segment; <=32 keys -> shfl bitonic
    int nw = s_nw;
    if (nw > 256) nw = 256;
    for (int t = wid; t < nw; t += 32) {
        unsigned e  = s_wl[t];
        int off = (int)(e >> 8);
        int cnt = (int)(e & 255u);
        if (cnt <= 32) {
            unsigned long long v = (lane < cnt && off + lane < SELCAP)
                                   ? sbuf[off + lane] : 0ull;
#pragma unroll
            for (int k = 2; k <= 32; k <<= 1)
#pragma unroll
                for (int j = k >> 1; j >= 1; j >>= 1)
                    v = bt_shfl(v, j, k, lane);
            if (lane < cnt && off + lane < SELCAP) sbuf[off + lane] = v;
        } else if (lane == 0) {            // fallback (never seen: max ~30/bin)
            for (int i = 1; i < cnt && off + i < SELCAP; ++i) {
                unsigned long long key = sbuf[off + i];
                int j = i - 1;
                while (j >= 0 && sbuf[off + j] < key) {
                    sbuf[off + j + 1] = sbuf[off + j];
                    --j;
                }
                sbuf[off + j + 1] = key;
            }
        }
    }
    __syncthreads();

    // decode top-512
    if (tid < KTOP) {
        unsigned long long key = sbuf[tid];
        float X1 = 0.f, Y1 = 0.f, X2 = 0.f, Y2 = 0.f, score = -1.0f;
        if (key != 0ull) {
            score = __uint_as_float((unsigned)(key >> 32));
            unsigned idx = 0xffffffffu - (unsigned)(key & 0xffffffffu);
            float4 l = __ldg(&loc[idx]);
            float4 p = __ldg(&priors[idx]);
            float cx = __fadd_rn(p.x, __fmul_rn(__fmul_rn(l.x, 0.1f), p.z));
            float cy = __fadd_rn(p.y, __fmul_rn(__fmul_rn(l.y, 0.1f), p.w));
            float w  = __fmul_rn(p.z, expf(__fmul_rn(l.z, 0.2f)));
            float h  = __fmul_rn(p.w, expf(__fmul_rn(l.w, 0.2f)));
            float x1 = __fsub_rn(cx, __fmul_rn(w, 0.5f));
            float y1 = __fsub_rn(cy, __fmul_rn(h, 0.5f));
            float x2 = __fadd_rn(x1, w);
            float y2 = __fadd_rn(y1, h);
            X1 = __fmul_rn(x1, 2048.0f);
            Y1 = __fmul_rn(y1, 2048.0f);
            X2 = __fmul_rn(x2, 2048.0f);
            Y2 = __fmul_rn(y2, 2048.0f);
        }
        g_box[tid]   = make_float4(X1, Y1, X2, Y2);
        g_area[tid]  = __fmul_rn(__fadd_rn(__fsub_rn(X2, X1), 1.0f),
                                 __fadd_rn(__fsub_rn(Y2, Y1), 1.0f));
        g_score[tid] = score;
    }
}

// ---------------------------------------------------------------------------
// K3: 512x512 suppression bitmask; no join, launch boundary is the barrier.
// ---------------------------------------------------------------------------
__global__ void __launch_bounds__(256) k_iou() {
    int T  = blockIdx.x * 256 + threadIdx.x;   // 0..32767
    int i  = T >> 6;
    int j0 = (T & 63) << 3;
    unsigned bits = 0u;
    float si = g_score[i];
    if (si > 0.0f) {
        float4 bi = g_box[i];
        float  ai = g_area[i];
#pragma unroll
        for (int b = 0; b < 8; ++b) {
            int j = j0 + b;
            float4 bj = g_box[j];
            float xx1 = fmaxf(bi.x, bj.x);
            float yy1 = fmaxf(bi.y, bj.y);
            float xx2 = fminf(bi.z, bj.z);
            float yy2 = fminf(bi.w, bj.w);
            float w = fmaxf(__fadd_rn(__fsub_rn(xx2, xx1), 1.0f), 0.0f);
            float h = fmaxf(__fadd_rn(__fsub_rn(yy2, yy1), 1.0f), 0.0f);
            float inter = __fmul_rn(w, h);
            float uni = __fsub_rn(__fadd_rn(ai, g_area[j]), inter);
            if (j > i && inter > __fmul_rn(0.4f, uni)) bits |= 1u << b;
        }
    }
    ((unsigned char*)g_mask32)[T] = (unsigned char)bits;
}

// ---------------------------------------------------------------------------
// K4: single block of 512: greedy NMS + output + histogram reset.
// Round-8 closure body (measured best) + halved cross-chunk (round 13).
// ---------------------------------------------------------------------------
#define DLOAD(r) unsigned d##r = um[(cb + r) * 16 + c];   // same addr = bcast
#define DSTEP(r) if (!(val & (1u << r))) val |= d##r;
#define REP32(M) M(0) M(1) M(2) M(3) M(4) M(5) M(6) M(7) \
                 M(8) M(9) M(10) M(11) M(12) M(13) M(14) M(15) \
                 M(16) M(17) M(18) M(19) M(20) M(21) M(22) M(23) \
                 M(24) M(25) M(26) M(27) M(28) M(29) M(30) M(31)

__global__ void __launch_bounds__(512, 1) k_nms(float* __restrict__ out) {
    __shared__ __align__(16) unsigned um[KTOP * 16];   // 32KB
    __shared__ unsigned s_keepw[16];
    int tid = threadIdx.x;
    for (int w = tid; w < KTOP * 4; w += 512)
        ((uint4*)um)[w] = ((const uint4*)g_mask32)[w];
    __syncthreads();

    if (tid < 32) {
        int lane = tid;
        int wlo  = lane & 15;
        int rb   = (lane < 16) ? 0 : 16;  // row split across the warp
        unsigned rem = 0u;
        for (int c = 0; c < 16; ++c) {
            unsigned val = __shfl_sync(0xffffffffu, rem, c);
            int cb = c * 32;
            REP32(DLOAD)                  // broadcast LDS into named regs
            REP32(DSTEP)                  // 32-step serial closure
            unsigned keep = ~val;
            // cross-chunk: 16 gated ORs per lane (rows split 0-15 / 16-31)
            unsigned acc = 0u;
#pragma unroll
            for (int q = 0; q < 16; ++q) {
                int r = rb + q;
                unsigned m = um[(cb + r) * 16 + wlo];
                acc |= ((keep >> r) & 1u) ? m : 0u;
            }
            acc |= __shfl_xor_sync(0xffffffffu, acc, 16);
            if (lane < 16) rem |= acc;
        }
        if (tid < 16) s_keepw[tid] = rem;
    }
    __syncthreads();

    const float inv = 1.0f / 2048.0f;     // exact
    if (tid < KTOP) {
        int r = tid;
        float sc = g_score[r];
        bool kept = (sc > 0.0f) && !((s_keepw[r >> 5] >> (r & 31)) & 1u);
        float4 b = g_box[r];
        out[r * 5 + 0] = kept ? __fmul_rn(b.x, inv) : 0.0f;
        out[r * 5 + 1] = kept ? __fmul_rn(b.y, inv) : 0.0f;
        out[r * 5 + 2] = kept ? __fmul_rn(b.z, inv) : 0.0f;
        out[r * 5 + 3] = kept ? __fmul_rn(b.w, inv) : 0.0f;
        out[r * 5 + 4] = kept ? sc : 0.0f;
    }

    // histogram reset for the next graph replay (zero-initialized at load)
    for (int i = tid; i < NB2; i += 512) g_hist[i] = 0;
}

// ---------------------------------------------------------------------------
extern "C" void kernel_launch(void* const* d_in, const int* in_sizes, int n_in,
                              void* d_out, int out_size) {
    const float4* loc    = (const float4*)d_in[0];   // [N,4]
    const float4* conf4  = (const float4*)d_in[1];   // [N,2] as float4 pairs
    const float4* priors = (const float4*)d_in[2];   // [N,4]
    float* out = (float*)d_out;                      // [512,5]
    int n  = in_sizes[0] / 4;
    int n4 = n >> 1;

    k_scan<<<(n4 + 1023) / 1024, 256>>>(conf4, n4);
    k_mid<<<1, 1024>>>(loc, priors);
    k_iou<<<128, 256>>>();
    k_nms<<<1, 512>>>(out);
}